// round 7
// baseline (speedup 1.0000x reference)
#include <cuda_runtime.h>

#define NMAX 100000
#define HID 256
#define EMB 128

#define QS 65535.0f
#define QI 1.5259021896696422e-05f   // 1/65535

// ---------------- scratch (static device globals; no allocation) -------------
__device__ int            g_degc[NMAX];            // in-degree COUNT (deg = c+1)
__device__ unsigned short g_disq[NMAX];            // dis quantized to u16 (scale 65535)
__device__ unsigned int   g_tq[NMAX];              // integer sum of quantized dis[src]
__device__ float          g_thr[HID];              // sorted relu breakpoints
__device__ __align__(16) float2 g_tab[(HID + 1) * EMB]; // per-interval (A, C)

// ---- per-block edge dtype detection (reads first 32B of src half, cached) ---
__device__ __forceinline__ int edges_is32(const void* edges) {
    const unsigned long long* p = (const unsigned long long*)edges;
    unsigned long long x = p[0] | p[1] | p[2] | p[3];
    return (unsigned int)(x >> 32) != 0u;  // hi words nonzero => packed int32 pairs
}

// ---- K_A: union kernel -------------------------------------------------------
// blocks [0, degBlocks):       degree atomics over dst (16 edges/thread)
// blocks [degBlocks, +EMB):    per-column table build (own in-smem sort)
// The tab blocks are latency-bound and overlap with the L2-bound deg blocks.
__global__ void k_degtab(const void* __restrict__ edges, int E, int degBlocks,
                         const float* __restrict__ W1, const float* __restrict__ b1,
                         const float* __restrict__ W2, const float* __restrict__ b2) {
    if (blockIdx.x < degBlocks) {
        int is32 = edges_is32(edges);
        int i = (blockIdx.x * blockDim.x + threadIdx.x) * 16;
        if (i >= E) return;
        if (is32) {
            const int* p = (const int*)edges + E;  // dst half
            if (i + 16 <= E) {
                const int4* q = (const int4*)(p + i);
                #pragma unroll
                for (int u = 0; u < 4; u++) {
                    int4 v = __ldcs(q + u);
                    atomicAdd(&g_degc[v.x], 1); atomicAdd(&g_degc[v.y], 1);
                    atomicAdd(&g_degc[v.z], 1); atomicAdd(&g_degc[v.w], 1);
                }
            } else {
                for (int j = i; j < E; j++) atomicAdd(&g_degc[p[j]], 1);
            }
        } else {
            const long long* p = (const long long*)edges + E;
            if (i + 16 <= E) {
                const int4* q = (const int4*)(p + i);
                #pragma unroll
                for (int u = 0; u < 8; u++) {
                    int4 v = __ldcs(q + u);
                    atomicAdd(&g_degc[v.x], 1); atomicAdd(&g_degc[v.z], 1);
                }
            } else {
                for (int j = i; j < E; j++) atomicAdd(&g_degc[(int)p[j]], 1);
            }
        }
        return;
    }

    // ---------------- table-build block (column j) ---------------------------
    __shared__ float key[HID];
    __shared__ int   idx[HID];
    __shared__ float sa[HID], sc[HID];  // deltas -> scan
    __shared__ float ra[HID], rc[HID];  // base terms -> reduction
    int j = blockIdx.x - degBlocks;
    int t = threadIdx.x;

    // relu(s*w+b) crossing for s>0: thr=-b/w if (w>0,b<0) or (w<0,b>0)
    float w = W1[t], b = b1[t];
    float thr = 3.0e38f;
    if ((w > 0.f && b < 0.f) || (w < 0.f && b > 0.f)) thr = -b / w;
    key[t] = thr; idx[t] = t;

    // base term (h = t): active as s->0+
    float w2 = __ldg(&W2[t * EMB + j]);
    bool act = (b > 0.f) || (b == 0.f && w > 0.f);
    ra[t] = act ? w * w2 : 0.f;
    rc[t] = act ? b * w2 : 0.f;
    __syncthreads();

    // bitonic sort (key, idx) ascending — redundant per block, fully parallel
    for (int k = 2; k <= HID; k <<= 1) {
        for (int s = k >> 1; s > 0; s >>= 1) {
            int p = t ^ s;
            if (p > t) {
                bool up = ((t & k) == 0);
                float ka = key[t], kb = key[p];
                if ((ka > kb) == up) {
                    key[t] = kb; key[p] = ka;
                    int ia = idx[t]; idx[t] = idx[p]; idx[p] = ia;
                }
            }
            __syncthreads();
        }
    }
    if (j == 0) g_thr[t] = key[t];  // publish thresholds once (block degBlocks)

    // delta term at sorted position t (toggled term is exactly 0 at its
    // breakpoint => interval boundary handling is value-exact)
    int h = idx[t];
    float wh = W1[h], bh = b1[h];
    float w2h = __ldg(&W2[h * EMB + j]);
    float d = (wh > 0.f && bh < 0.f) ? 1.f : ((wh < 0.f && bh > 0.f) ? -1.f : 0.f);
    sa[t] = d * wh * w2h;
    sc[t] = d * bh * w2h;
    __syncthreads();

    // block reduction of base
    #pragma unroll
    for (int s = HID / 2; s > 0; s >>= 1) {
        if (t < s) { ra[t] += ra[t + s]; rc[t] += rc[t + s]; }
        __syncthreads();
    }
    float A0 = ra[0];
    float C0 = rc[0] + b2[j];

    // inclusive Hillis-Steele scan of deltas
    #pragma unroll
    for (int off = 1; off < HID; off <<= 1) {
        float va = 0.f, vc = 0.f;
        if (t >= off) { va = sa[t - off]; vc = sc[t - off]; }
        __syncthreads();
        if (t >= off) { sa[t] += va; sc[t] += vc; }
        __syncthreads();
    }

    if (t == 0) g_tab[j] = make_float2(A0, C0);
    g_tab[(t + 1) * EMB + j] = make_float2(A0 + sa[t], C0 + sc[t]);
}

// ---- K_B: quantize dis to u16, 4 nodes/thread, packed u32 stores ------------
__global__ void k_dis(int N) {
    int n = (blockIdx.x * blockDim.x + threadIdx.x) * 4;
    if (n >= N) return;
    if (n + 4 <= N) {
        int4 c = *(const int4*)&g_degc[n];
        unsigned int q0 = __float2uint_rn(rsqrtf((float)(c.x + 1)) * QS);
        unsigned int q1 = __float2uint_rn(rsqrtf((float)(c.y + 1)) * QS);
        unsigned int q2 = __float2uint_rn(rsqrtf((float)(c.z + 1)) * QS);
        unsigned int q3 = __float2uint_rn(rsqrtf((float)(c.w + 1)) * QS);
        *(uint2*)&g_disq[n] = make_uint2(q0 | (q1 << 16), q2 | (q3 << 16));
    } else {
        for (int m = n; m < N; m++)
            g_disq[m] = (unsigned short)__float2uint_rn(rsqrtf((float)(g_degc[m] + 1)) * QS);
    }
}

// ---- K_C: tq[dst] += disq[src]  (u16 L1 gather + u32 L2 atomic) -------------
__device__ __forceinline__ void scat1(int src, int dst) {
    unsigned int q = (unsigned int)__ldg(&g_disq[src]);
    atomicAdd(&g_tq[dst], q);
}
__global__ void k_scat(const void* __restrict__ edges, int E) {
    int is32 = edges_is32(edges);
    int i = (blockIdx.x * blockDim.x + threadIdx.x) * 16;
    if (i >= E) return;
    if (is32) {
        const int* ps = (const int*)edges;
        const int* pd = ps + E;
        if (i + 16 <= E) {
            const int4* qs = (const int4*)(ps + i);
            const int4* qd = (const int4*)(pd + i);
            #pragma unroll
            for (int u = 0; u < 4; u++) {
                int4 s = __ldcs(qs + u);
                int4 d = __ldcs(qd + u);
                scat1(s.x, d.x); scat1(s.y, d.y); scat1(s.z, d.z); scat1(s.w, d.w);
            }
        } else {
            for (int j = i; j < E; j++) scat1(ps[j], pd[j]);
        }
    } else {
        const long long* ps = (const long long*)edges;
        const long long* pd = ps + E;
        if (i + 16 <= E) {
            const int4* qs = (const int4*)(ps + i);
            const int4* qd = (const int4*)(pd + i);
            #pragma unroll
            for (int u = 0; u < 8; u++) {
                int4 s = __ldcs(qs + u);
                int4 d = __ldcs(qd + u);
                scat1(s.x, d.x); scat1(s.z, d.z);
            }
        } else {
            for (int j = i; j < E; j++) scat1((int)ps[j], (int)pd[j]);
        }
    }
}

// ---- K_D: per-node s + binary search + 128 affine sigmoids (2 nodes/thr) ----
__global__ void k_out(float* __restrict__ out, int N) {
    __shared__ float sthr[HID];
    for (int i = threadIdx.x; i < HID; i += blockDim.x) sthr[i] = g_thr[i];
    __syncthreads();

    int n0 = (blockIdx.x * blockDim.x + threadIdx.x) * 2;
    if (n0 >= N) return;
    bool has2 = (n0 + 1 < N) && ((N & 1) == 0);
    int n1 = has2 ? n0 + 1 : n0;

    float d0 = rsqrtf((float)(g_degc[n0] + 1));
    float d1 = rsqrtf((float)(g_degc[n1] + 1));
    float s0 = d0 * ((float)g_tq[n0] * QI + d0);
    float s1 = d1 * ((float)g_tq[n1] * QI + d1);

    int lo0 = 0, hi0 = HID, lo1 = 0, hi1 = HID;
    #pragma unroll
    for (int it = 0; it < 8; it++) {
        int m0 = (lo0 + hi0) >> 1;
        if (sthr[m0] < s0) lo0 = m0 + 1; else hi0 = m0;
        int m1 = (lo1 + hi1) >> 1;
        if (sthr[m1] < s1) lo1 = m1 + 1; else hi1 = m1;
    }

    const float4* __restrict__ r0 = (const float4*)(g_tab + lo0 * EMB);
    const float4* __restrict__ r1 = (const float4*)(g_tab + lo1 * EMB);

    if (has2) {
        #pragma unroll 8
        for (int jj = 0; jj < EMB / 2; jj++) {
            float4 va = __ldg(&r0[jj]);
            float4 vb = __ldg(&r1[jj]);
            float xa0 = fmaf(s0, va.x, va.y), xa1 = fmaf(s0, va.z, va.w);
            float xb0 = fmaf(s1, vb.x, vb.y), xb1 = fmaf(s1, vb.z, vb.w);
            float ya0 = __fdividef(1.f, 1.f + __expf(-xa0));
            float ya1 = __fdividef(1.f, 1.f + __expf(-xa1));
            float yb0 = __fdividef(1.f, 1.f + __expf(-xb0));
            float yb1 = __fdividef(1.f, 1.f + __expf(-xb1));
            int j = jj * 2;
            *(float2*)&out[j * N + n0]       = make_float2(ya0, yb0);
            *(float2*)&out[(j + 1) * N + n0] = make_float2(ya1, yb1);
        }
    } else {
        #pragma unroll 8
        for (int jj = 0; jj < EMB / 2; jj++) {
            float4 va = __ldg(&r0[jj]);
            float xa0 = fmaf(s0, va.x, va.y), xa1 = fmaf(s0, va.z, va.w);
            int j = jj * 2;
            out[j * N + n0]       = __fdividef(1.f, 1.f + __expf(-xa0));
            out[(j + 1) * N + n0] = __fdividef(1.f, 1.f + __expf(-xa1));
        }
    }
}

// ---------------- launch ------------------------------------------------------
extern "C" void kernel_launch(void* const* d_in, const int* in_sizes, int n_in,
                              void* d_out, int out_size) {
    const void*  edges = d_in[0];
    const float* W1    = (const float*)d_in[1];
    const float* b1    = (const float*)d_in[2];
    const float* W2    = (const float*)d_in[3];
    const float* b2    = (const float*)d_in[4];
    int E = in_sizes[0] / 2;
    int N = out_size / EMB;
    if (N > NMAX) N = NMAX;

    const int TB = 256;
    int gE = (E + TB * 16 - 1) / (TB * 16);
    int gD = (N + TB * 4 - 1) / (TB * 4);
    int gO = (N + TB * 2 - 1) / (TB * 2);

    void *pdeg = nullptr, *ptq = nullptr;
    cudaGetSymbolAddress(&pdeg, g_degc);
    cudaGetSymbolAddress(&ptq, g_tq);
    cudaMemsetAsync(pdeg, 0, (size_t)N * sizeof(int), 0);
    cudaMemsetAsync(ptq,  0, (size_t)N * sizeof(unsigned int), 0);

    k_degtab<<<gE + EMB, TB>>>(edges, E, gE, W1, b1, W2, b2);
    k_dis   <<<gD, TB>>>(N);
    k_scat  <<<gE, TB>>>(edges, E);
    k_out   <<<gO, TB>>>((float*)d_out, N);
}

// round 8
// speedup vs baseline: 1.1751x; 1.1751x over previous
#include <cuda_runtime.h>

#define NMAX 100000
#define HID 256
#define EMB 128

#define QS 65535.0f
#define QI 1.5259021896696422e-05f   // 1/65535

// ---------------- scratch (static device globals; no allocation) -------------
__device__ int            g_degc[NMAX];            // in-degree COUNT (deg = c+1)
__device__ unsigned short g_disq[NMAX];            // dis quantized to u16 (scale 65535)
__device__ unsigned int   g_tq[NMAX];              // integer sum of quantized dis[src]
__device__ float          g_thr[HID];              // sorted relu breakpoints
__device__ int            g_sidx[HID];             // permutation: sorted pos -> h
__device__ __align__(16) float2 g_tab[(HID + 1) * EMB]; // per-interval (A, C)

// ---- per-block edge dtype detection (reads first 32B of src half, cached) ---
__device__ __forceinline__ int edges_is32(const void* edges) {
    const unsigned long long* p = (const unsigned long long*)edges;
    unsigned long long x = p[0] | p[1] | p[2] | p[3];
    return (unsigned int)(x >> 32) != 0u;  // hi words nonzero => packed int32 pairs
}

// ---- K1: init degc/tq; last block sorts relu breakpoints --------------------
__global__ void k_init(const float* __restrict__ W1, const float* __restrict__ b1,
                       int N) {
    if (blockIdx.x == gridDim.x - 1) {
        int t = threadIdx.x;
        __shared__ float key[HID];
        __shared__ int   idx[HID];
        // relu(s*w+b) crossing for s>0: thr=-b/w if (w>0,b<0) or (w<0,b>0)
        float w = W1[t], b = b1[t];
        float thr = 3.0e38f;
        if ((w > 0.f && b < 0.f) || (w < 0.f && b > 0.f)) thr = -b / w;
        key[t] = thr; idx[t] = t;
        __syncthreads();
        for (int k = 2; k <= HID; k <<= 1) {
            for (int j = k >> 1; j > 0; j >>= 1) {
                int p = t ^ j;
                if (p > t) {
                    bool up = ((t & k) == 0);
                    float ka = key[t], kb = key[p];
                    if ((ka > kb) == up) {
                        key[t] = kb; key[p] = ka;
                        int ia = idx[t]; idx[t] = idx[p]; idx[p] = ia;
                    }
                }
                __syncthreads();
            }
        }
        g_thr[t] = key[t];
        g_sidx[t] = idx[t];
    } else {
        int n = blockIdx.x * blockDim.x + threadIdx.x;
        if (n < N) { g_degc[n] = 0; g_tq[n] = 0u; }
    }
}

// ---- K2: in-degree count over dst (8 edges / thread, streaming loads) -------
__global__ void k_deg(const void* __restrict__ edges, int E) {
    int is32 = edges_is32(edges);
    int i = (blockIdx.x * blockDim.x + threadIdx.x) * 8;
    if (i >= E) return;
    if (is32) {
        const int* p = (const int*)edges + E;  // dst half
        if (i + 8 <= E) {
            const int4* q = (const int4*)(p + i);
            int4 a = __ldcs(q), b = __ldcs(q + 1);
            atomicAdd(&g_degc[a.x], 1); atomicAdd(&g_degc[a.y], 1);
            atomicAdd(&g_degc[a.z], 1); atomicAdd(&g_degc[a.w], 1);
            atomicAdd(&g_degc[b.x], 1); atomicAdd(&g_degc[b.y], 1);
            atomicAdd(&g_degc[b.z], 1); atomicAdd(&g_degc[b.w], 1);
        } else {
            for (int j = i; j < E; j++) atomicAdd(&g_degc[p[j]], 1);
        }
    } else {
        const long long* p = (const long long*)edges + E;
        if (i + 8 <= E) {
            const int4* q = (const int4*)(p + i);
            int4 a = __ldcs(q), b = __ldcs(q + 1), c = __ldcs(q + 2), d = __ldcs(q + 3);
            atomicAdd(&g_degc[a.x], 1); atomicAdd(&g_degc[a.z], 1);
            atomicAdd(&g_degc[b.x], 1); atomicAdd(&g_degc[b.z], 1);
            atomicAdd(&g_degc[c.x], 1); atomicAdd(&g_degc[c.z], 1);
            atomicAdd(&g_degc[d.x], 1); atomicAdd(&g_degc[d.z], 1);
        } else {
            for (int j = i; j < E; j++) atomicAdd(&g_degc[(int)p[j]], 1);
        }
    }
}

// ---- K3 union: blocks [0,disBlocks) quantize dis; remaining EMB blocks build
//      the per-interval tables. Both parts fit in one wave and overlap. -------
__global__ void k_distab(int N, int disBlocks,
                         const float* __restrict__ W1, const float* __restrict__ b1,
                         const float* __restrict__ W2, const float* __restrict__ b2) {
    if (blockIdx.x < disBlocks) {
        int n = (blockIdx.x * blockDim.x + threadIdx.x) * 4;
        if (n >= N) return;
        if (n + 4 <= N) {
            int4 c = *(const int4*)&g_degc[n];
            unsigned int q0 = __float2uint_rn(rsqrtf((float)(c.x + 1)) * QS);
            unsigned int q1 = __float2uint_rn(rsqrtf((float)(c.y + 1)) * QS);
            unsigned int q2 = __float2uint_rn(rsqrtf((float)(c.z + 1)) * QS);
            unsigned int q3 = __float2uint_rn(rsqrtf((float)(c.w + 1)) * QS);
            *(uint2*)&g_disq[n] = make_uint2(q0 | (q1 << 16), q2 | (q3 << 16));
        } else {
            for (int m = n; m < N; m++)
                g_disq[m] = (unsigned short)__float2uint_rn(rsqrtf((float)(g_degc[m] + 1)) * QS);
        }
        return;
    }

    // ---- table-build block (column j): base + delta prefix-scan -------------
    __shared__ float sa[HID], sc[HID];  // deltas -> scan
    __shared__ float ra[HID], rc[HID];  // base terms -> reduction
    int j = blockIdx.x - disBlocks;
    int t = threadIdx.x;
    if (t >= HID) return;

    float w = W1[t], b = b1[t];
    float w2 = __ldg(&W2[t * EMB + j]);
    bool act = (b > 0.f) || (b == 0.f && w > 0.f);
    ra[t] = act ? w * w2 : 0.f;
    rc[t] = act ? b * w2 : 0.f;

    // delta at sorted position t (toggled term is exactly 0 at its breakpoint
    // => interval boundary handling is value-exact)
    int h = g_sidx[t];
    float wh = W1[h], bh = b1[h];
    float w2h = __ldg(&W2[h * EMB + j]);
    float d = (wh > 0.f && bh < 0.f) ? 1.f : ((wh < 0.f && bh > 0.f) ? -1.f : 0.f);
    sa[t] = d * wh * w2h;
    sc[t] = d * bh * w2h;
    __syncthreads();

    #pragma unroll
    for (int s = HID / 2; s > 0; s >>= 1) {
        if (t < s) { ra[t] += ra[t + s]; rc[t] += rc[t + s]; }
        __syncthreads();
    }
    float A0 = ra[0];
    float C0 = rc[0] + b2[j];

    #pragma unroll
    for (int off = 1; off < HID; off <<= 1) {
        float va = 0.f, vc = 0.f;
        if (t >= off) { va = sa[t - off]; vc = sc[t - off]; }
        __syncthreads();
        if (t >= off) { sa[t] += va; sc[t] += vc; }
        __syncthreads();
    }

    if (t == 0) g_tab[j] = make_float2(A0, C0);
    g_tab[(t + 1) * EMB + j] = make_float2(A0 + sa[t], C0 + sc[t]);
}

// ---- K4: tq[dst] += disq[src]  (u16 L1 gather + u32 L2 atomic) --------------
__device__ __forceinline__ void scat1(int src, int dst) {
    unsigned int q = (unsigned int)__ldg(&g_disq[src]);
    atomicAdd(&g_tq[dst], q);
}
__global__ void k_scat(const void* __restrict__ edges, int E) {
    int is32 = edges_is32(edges);
    int i = (blockIdx.x * blockDim.x + threadIdx.x) * 8;
    if (i >= E) return;
    if (is32) {
        const int* ps = (const int*)edges;
        const int* pd = ps + E;
        if (i + 8 <= E) {
            const int4* qs = (const int4*)(ps + i);
            const int4* qd = (const int4*)(pd + i);
            int4 s0 = __ldcs(qs), s1 = __ldcs(qs + 1);
            int4 d0 = __ldcs(qd), d1 = __ldcs(qd + 1);
            scat1(s0.x, d0.x); scat1(s0.y, d0.y); scat1(s0.z, d0.z); scat1(s0.w, d0.w);
            scat1(s1.x, d1.x); scat1(s1.y, d1.y); scat1(s1.z, d1.z); scat1(s1.w, d1.w);
        } else {
            for (int j = i; j < E; j++) scat1(ps[j], pd[j]);
        }
    } else {
        const long long* ps = (const long long*)edges;
        const long long* pd = ps + E;
        if (i + 8 <= E) {
            const int4* qs = (const int4*)(ps + i);
            const int4* qd = (const int4*)(pd + i);
            #pragma unroll
            for (int u = 0; u < 4; u++) {
                int4 s = __ldcs(qs + u);
                int4 d = __ldcs(qd + u);
                scat1(s.x, d.x); scat1(s.z, d.z);
            }
        } else {
            for (int j = i; j < E; j++) scat1((int)ps[j], (int)pd[j]);
        }
    }
}

// ---- K5: output. grid (nodeBlocks, 4): each thread 2 nodes x 32 columns -----
__global__ void k_out(float* __restrict__ out, int N) {
    __shared__ float sthr[HID];
    for (int i = threadIdx.x; i < HID; i += blockDim.x) sthr[i] = g_thr[i];
    __syncthreads();

    int n0 = (blockIdx.x * blockDim.x + threadIdx.x) * 2;
    if (n0 >= N) return;
    int jbase = blockIdx.y * (EMB / 4);   // 32 columns per y-slice
    bool has2 = (n0 + 1 < N) && ((N & 1) == 0);
    int n1 = has2 ? n0 + 1 : n0;

    float d0 = rsqrtf((float)(g_degc[n0] + 1));
    float d1 = rsqrtf((float)(g_degc[n1] + 1));
    float s0 = d0 * ((float)g_tq[n0] * QI + d0);
    float s1 = d1 * ((float)g_tq[n1] * QI + d1);

    int lo0 = 0, hi0 = HID, lo1 = 0, hi1 = HID;
    #pragma unroll
    for (int it = 0; it < 8; it++) {
        int m0 = (lo0 + hi0) >> 1;
        if (sthr[m0] < s0) lo0 = m0 + 1; else hi0 = m0;
        int m1 = (lo1 + hi1) >> 1;
        if (sthr[m1] < s1) lo1 = m1 + 1; else hi1 = m1;
    }

    const float4* __restrict__ r0 = (const float4*)(g_tab + lo0 * EMB + jbase);
    const float4* __restrict__ r1 = (const float4*)(g_tab + lo1 * EMB + jbase);

    if (has2) {
        #pragma unroll
        for (int jj = 0; jj < EMB / 8; jj++) {       // 16 iters x 2 columns
            float4 va = __ldg(&r0[jj]);
            float4 vb = __ldg(&r1[jj]);
            float xa0 = fmaf(s0, va.x, va.y), xa1 = fmaf(s0, va.z, va.w);
            float xb0 = fmaf(s1, vb.x, vb.y), xb1 = fmaf(s1, vb.z, vb.w);
            float ya0 = __fdividef(1.f, 1.f + __expf(-xa0));
            float ya1 = __fdividef(1.f, 1.f + __expf(-xa1));
            float yb0 = __fdividef(1.f, 1.f + __expf(-xb0));
            float yb1 = __fdividef(1.f, 1.f + __expf(-xb1));
            int j = jbase + jj * 2;
            *(float2*)&out[j * N + n0]       = make_float2(ya0, yb0);
            *(float2*)&out[(j + 1) * N + n0] = make_float2(ya1, yb1);
        }
    } else {
        #pragma unroll
        for (int jj = 0; jj < EMB / 8; jj++) {
            float4 va = __ldg(&r0[jj]);
            float xa0 = fmaf(s0, va.x, va.y), xa1 = fmaf(s0, va.z, va.w);
            int j = jbase + jj * 2;
            out[j * N + n0]       = __fdividef(1.f, 1.f + __expf(-xa0));
            out[(j + 1) * N + n0] = __fdividef(1.f, 1.f + __expf(-xa1));
        }
    }
}

// ---------------- launch ------------------------------------------------------
extern "C" void kernel_launch(void* const* d_in, const int* in_sizes, int n_in,
                              void* d_out, int out_size) {
    const void*  edges = d_in[0];
    const float* W1    = (const float*)d_in[1];
    const float* b1    = (const float*)d_in[2];
    const float* W2    = (const float*)d_in[3];
    const float* b2    = (const float*)d_in[4];
    int E = in_sizes[0] / 2;
    int N = out_size / EMB;
    if (N > NMAX) N = NMAX;

    const int TB = 256;
    int gN = (N + TB - 1) / TB;
    int gE = (E + TB * 8 - 1) / (TB * 8);
    int gD = (N + TB * 4 - 1) / (TB * 4);
    int gO = (N + TB * 2 - 1) / (TB * 2);

    k_init  <<<gN + 1, TB>>>(W1, b1, N);
    k_deg   <<<gE, TB>>>(edges, E);
    k_distab<<<gD + EMB, TB>>>(N, gD, W1, b1, W2, b2);
    k_scat  <<<gE, TB>>>(edges, E);
    k_out   <<<dim3(gO, 4), TB>>>((float*)d_out, N);
}

// round 9
// speedup vs baseline: 1.2134x; 1.0327x over previous
#include <cuda_runtime.h>

#define NMAX 100000
#define HID 256
#define EMB 128

#define QS 65535.0f
#define QI 1.5259021896696422e-05f   // 1/65535

// ---------------- scratch (static device globals; no allocation) -------------
__device__ int            g_degc[NMAX];            // in-degree COUNT (deg = c+1)
__device__ unsigned short g_disq[NMAX];            // dis quantized to u16 (scale 65535)
__device__ unsigned int   g_tq[NMAX];              // integer sum of quantized dis[src]
__device__ float          g_thr[HID];              // sorted relu breakpoints
__device__ int            g_sidx[HID];             // permutation: sorted pos -> h
__device__ __align__(16) float2 g_tab[(HID + 1) * EMB]; // per-interval (A, C)

// ---- per-block edge dtype detection (reads first 32B of src half, cached) ---
__device__ __forceinline__ int edges_is32(const void* edges) {
    const unsigned long long* p = (const unsigned long long*)edges;
    unsigned long long x = p[0] | p[1] | p[2] | p[3];
    return (unsigned int)(x >> 32) != 0u;  // hi words nonzero => packed int32 pairs
}

// ---- K1: init degc/tq; last block sorts relu breakpoints --------------------
__global__ void k_init(const float* __restrict__ W1, const float* __restrict__ b1,
                       int N) {
    if (blockIdx.x == gridDim.x - 1) {
        int t = threadIdx.x;
        __shared__ float key[HID];
        __shared__ int   idx[HID];
        // relu(s*w+b) crossing for s>0: thr=-b/w if (w>0,b<0) or (w<0,b>0)
        float w = W1[t], b = b1[t];
        float thr = 3.0e38f;
        if ((w > 0.f && b < 0.f) || (w < 0.f && b > 0.f)) thr = -b / w;
        key[t] = thr; idx[t] = t;
        __syncthreads();
        for (int k = 2; k <= HID; k <<= 1) {
            for (int j = k >> 1; j > 0; j >>= 1) {
                int p = t ^ j;
                if (p > t) {
                    bool up = ((t & k) == 0);
                    float ka = key[t], kb = key[p];
                    if ((ka > kb) == up) {
                        key[t] = kb; key[p] = ka;
                        int ia = idx[t]; idx[t] = idx[p]; idx[p] = ia;
                    }
                }
                __syncthreads();
            }
        }
        g_thr[t] = key[t];
        g_sidx[t] = idx[t];
    } else {
        int n = blockIdx.x * blockDim.x + threadIdx.x;
        if (n < N) { g_degc[n] = 0; g_tq[n] = 0u; }
    }
}

// ---- K2: in-degree count over dst (4 edges / thread) ------------------------
// dst half loaded with __ldg (default caching) so it stays L2-resident for
// k_scat's re-read of the same 25.6MB.
__global__ void __launch_bounds__(256, 8) k_deg(const void* __restrict__ edges, int E) {
    int is32 = edges_is32(edges);
    int i = (blockIdx.x * blockDim.x + threadIdx.x) * 4;
    if (i >= E) return;
    if (is32) {
        const int* p = (const int*)edges + E;  // dst half
        if (i + 4 <= E) {
            int4 v = __ldg((const int4*)(p + i));
            atomicAdd(&g_degc[v.x], 1); atomicAdd(&g_degc[v.y], 1);
            atomicAdd(&g_degc[v.z], 1); atomicAdd(&g_degc[v.w], 1);
        } else {
            for (int j = i; j < E; j++) atomicAdd(&g_degc[p[j]], 1);
        }
    } else {
        const long long* p = (const long long*)edges + E;
        if (i + 4 <= E) {
            const int4* q = (const int4*)(p + i);
            int4 a = __ldg(q), b = __ldg(q + 1);
            atomicAdd(&g_degc[a.x], 1); atomicAdd(&g_degc[a.z], 1);
            atomicAdd(&g_degc[b.x], 1); atomicAdd(&g_degc[b.z], 1);
        } else {
            for (int j = i; j < E; j++) atomicAdd(&g_degc[(int)p[j]], 1);
        }
    }
}

// ---- K3 union: blocks [0,disBlocks) quantize dis; remaining EMB blocks build
//      the per-interval tables. Both parts fit in one wave and overlap. -------
__global__ void k_distab(int N, int disBlocks,
                         const float* __restrict__ W1, const float* __restrict__ b1,
                         const float* __restrict__ W2, const float* __restrict__ b2) {
    if (blockIdx.x < disBlocks) {
        int n = (blockIdx.x * blockDim.x + threadIdx.x) * 4;
        if (n >= N) return;
        if (n + 4 <= N) {
            int4 c = *(const int4*)&g_degc[n];
            unsigned int q0 = __float2uint_rn(rsqrtf((float)(c.x + 1)) * QS);
            unsigned int q1 = __float2uint_rn(rsqrtf((float)(c.y + 1)) * QS);
            unsigned int q2 = __float2uint_rn(rsqrtf((float)(c.z + 1)) * QS);
            unsigned int q3 = __float2uint_rn(rsqrtf((float)(c.w + 1)) * QS);
            *(uint2*)&g_disq[n] = make_uint2(q0 | (q1 << 16), q2 | (q3 << 16));
        } else {
            for (int m = n; m < N; m++)
                g_disq[m] = (unsigned short)__float2uint_rn(rsqrtf((float)(g_degc[m] + 1)) * QS);
        }
        return;
    }

    // ---- table-build block (column j): base + delta prefix-scan -------------
    __shared__ float sa[HID], sc[HID];  // deltas -> scan
    __shared__ float ra[HID], rc[HID];  // base terms -> reduction
    int j = blockIdx.x - disBlocks;
    int t = threadIdx.x;
    if (t >= HID) return;

    float w = W1[t], b = b1[t];
    float w2 = __ldg(&W2[t * EMB + j]);
    bool act = (b > 0.f) || (b == 0.f && w > 0.f);
    ra[t] = act ? w * w2 : 0.f;
    rc[t] = act ? b * w2 : 0.f;

    // delta at sorted position t (toggled term is exactly 0 at its breakpoint
    // => interval boundary handling is value-exact)
    int h = g_sidx[t];
    float wh = W1[h], bh = b1[h];
    float w2h = __ldg(&W2[h * EMB + j]);
    float d = (wh > 0.f && bh < 0.f) ? 1.f : ((wh < 0.f && bh > 0.f) ? -1.f : 0.f);
    sa[t] = d * wh * w2h;
    sc[t] = d * bh * w2h;
    __syncthreads();

    #pragma unroll
    for (int s = HID / 2; s > 0; s >>= 1) {
        if (t < s) { ra[t] += ra[t + s]; rc[t] += rc[t + s]; }
        __syncthreads();
    }
    float A0 = ra[0];
    float C0 = rc[0] + b2[j];

    #pragma unroll
    for (int off = 1; off < HID; off <<= 1) {
        float va = 0.f, vc = 0.f;
        if (t >= off) { va = sa[t - off]; vc = sc[t - off]; }
        __syncthreads();
        if (t >= off) { sa[t] += va; sc[t] += vc; }
        __syncthreads();
    }

    if (t == 0) g_tab[j] = make_float2(A0, C0);
    g_tab[(t + 1) * EMB + j] = make_float2(A0 + sa[t], C0 + sc[t]);
}

// ---- K4: tq[dst] += disq[src]  (u16 L1 gather + u32 L2 atomic) --------------
__device__ __forceinline__ void scat1(int src, int dst) {
    unsigned int q = (unsigned int)__ldg(&g_disq[src]);
    atomicAdd(&g_tq[dst], q);
}
__global__ void __launch_bounds__(256, 8) k_scat(const void* __restrict__ edges, int E) {
    int is32 = edges_is32(edges);
    int i = (blockIdx.x * blockDim.x + threadIdx.x) * 4;
    if (i >= E) return;
    if (is32) {
        const int* ps = (const int*)edges;
        const int* pd = ps + E;
        if (i + 4 <= E) {
            int4 s = __ldcs((const int4*)(ps + i));
            int4 d = __ldg((const int4*)(pd + i));
            scat1(s.x, d.x); scat1(s.y, d.y); scat1(s.z, d.z); scat1(s.w, d.w);
        } else {
            for (int j = i; j < E; j++) scat1(ps[j], pd[j]);
        }
    } else {
        const long long* ps = (const long long*)edges;
        const long long* pd = ps + E;
        if (i + 4 <= E) {
            const int4* qs = (const int4*)(ps + i);
            const int4* qd = (const int4*)(pd + i);
            int4 s0 = __ldcs(qs), s1 = __ldcs(qs + 1);
            int4 d0 = __ldg(qd),  d1 = __ldg(qd + 1);
            scat1(s0.x, d0.x); scat1(s0.z, d0.z);
            scat1(s1.x, d1.x); scat1(s1.z, d1.z);
        } else {
            for (int j = i; j < E; j++) scat1((int)ps[j], (int)pd[j]);
        }
    }
}

// ---- K5: output. grid (nodeBlocks, 4): each thread 2 nodes x 32 columns -----
__global__ void k_out(float* __restrict__ out, int N) {
    __shared__ float sthr[HID];
    for (int i = threadIdx.x; i < HID; i += blockDim.x) sthr[i] = g_thr[i];
    __syncthreads();

    int n0 = (blockIdx.x * blockDim.x + threadIdx.x) * 2;
    if (n0 >= N) return;
    int jbase = blockIdx.y * (EMB / 4);   // 32 columns per y-slice
    bool has2 = (n0 + 1 < N) && ((N & 1) == 0);
    int n1 = has2 ? n0 + 1 : n0;

    float d0 = rsqrtf((float)(g_degc[n0] + 1));
    float d1 = rsqrtf((float)(g_degc[n1] + 1));
    float s0 = d0 * ((float)g_tq[n0] * QI + d0);
    float s1 = d1 * ((float)g_tq[n1] * QI + d1);

    int lo0 = 0, hi0 = HID, lo1 = 0, hi1 = HID;
    #pragma unroll
    for (int it = 0; it < 8; it++) {
        int m0 = (lo0 + hi0) >> 1;
        if (sthr[m0] < s0) lo0 = m0 + 1; else hi0 = m0;
        int m1 = (lo1 + hi1) >> 1;
        if (sthr[m1] < s1) lo1 = m1 + 1; else hi1 = m1;
    }

    const float4* __restrict__ r0 = (const float4*)(g_tab + lo0 * EMB + jbase);
    const float4* __restrict__ r1 = (const float4*)(g_tab + lo1 * EMB + jbase);

    if (has2) {
        #pragma unroll
        for (int jj = 0; jj < EMB / 8; jj++) {       // 16 iters x 2 columns
            float4 va = __ldg(&r0[jj]);
            float4 vb = __ldg(&r1[jj]);
            float xa0 = fmaf(s0, va.x, va.y), xa1 = fmaf(s0, va.z, va.w);
            float xb0 = fmaf(s1, vb.x, vb.y), xb1 = fmaf(s1, vb.z, vb.w);
            float ya0 = __fdividef(1.f, 1.f + __expf(-xa0));
            float ya1 = __fdividef(1.f, 1.f + __expf(-xa1));
            float yb0 = __fdividef(1.f, 1.f + __expf(-xb0));
            float yb1 = __fdividef(1.f, 1.f + __expf(-xb1));
            int j = jbase + jj * 2;
            *(float2*)&out[j * N + n0]       = make_float2(ya0, yb0);
            *(float2*)&out[(j + 1) * N + n0] = make_float2(ya1, yb1);
        }
    } else {
        #pragma unroll
        for (int jj = 0; jj < EMB / 8; jj++) {
            float4 va = __ldg(&r0[jj]);
            float xa0 = fmaf(s0, va.x, va.y), xa1 = fmaf(s0, va.z, va.w);
            int j = jbase + jj * 2;
            out[j * N + n0]       = __fdividef(1.f, 1.f + __expf(-xa0));
            out[(j + 1) * N + n0] = __fdividef(1.f, 1.f + __expf(-xa1));
        }
    }
}

// ---------------- launch ------------------------------------------------------
extern "C" void kernel_launch(void* const* d_in, const int* in_sizes, int n_in,
                              void* d_out, int out_size) {
    const void*  edges = d_in[0];
    const float* W1    = (const float*)d_in[1];
    const float* b1    = (const float*)d_in[2];
    const float* W2    = (const float*)d_in[3];
    const float* b2    = (const float*)d_in[4];
    int E = in_sizes[0] / 2;
    int N = out_size / EMB;
    if (N > NMAX) N = NMAX;

    const int TB = 256;
    int gN = (N + TB - 1) / TB;
    int gE = (E + TB * 4 - 1) / (TB * 4);
    int gD = (N + TB * 4 - 1) / (TB * 4);
    int gO = (N + TB * 2 - 1) / (TB * 2);

    k_init  <<<gN + 1, TB>>>(W1, b1, N);
    k_deg   <<<gE, TB>>>(edges, E);
    k_distab<<<gD + EMB, TB>>>(N, gD, W1, b1, W2, b2);
    k_scat  <<<gE, TB>>>(edges, E);
    k_out   <<<dim3(gO, 4), TB>>>((float*)d_out, N);
}

// round 12
// speedup vs baseline: 1.2520x; 1.0317x over previous
#include <cuda_runtime.h>

#define NMAX 100000
#define HID 256
#define EMB 128

#define QS 65535.0f
#define QI 1.5259021896696422e-05f   // 1/65535

// ---------------- scratch (static device globals; no allocation) -------------
__device__ int            g_degc[NMAX];            // in-degree COUNT (deg = c+1)
__device__ unsigned short g_disq[NMAX];            // dis quantized to u16 (scale 65535)
__device__ unsigned int   g_tq[NMAX];              // integer sum of quantized dis[src]
__device__ float          g_thr[HID];              // sorted relu breakpoints
__device__ int            g_sidx[HID];             // permutation: sorted pos -> h
__device__ __align__(16) float2 g_tab[(HID + 1) * EMB]; // per-interval (A, C)

// ---- per-block edge dtype detection (reads first 32B of src half, cached) ---
__device__ __forceinline__ int edges_is32(const void* edges) {
    const unsigned long long* p = (const unsigned long long*)edges;
    unsigned long long x = p[0] | p[1] | p[2] | p[3];
    return (unsigned int)(x >> 32) != 0u;  // hi words nonzero => packed int32 pairs
}

// ---- K0: zero g_degc (4 nodes/thread, int4 stores) ---------------------------
__global__ void k_zero(int N) {
    int n = (blockIdx.x * blockDim.x + threadIdx.x) * 4;
    if (n >= N) return;
    if (n + 4 <= N) {
        *(int4*)&g_degc[n] = make_int4(0, 0, 0, 0);
    } else {
        for (int m = n; m < N; m++) g_degc[m] = 0;
    }
}

// ---- K1: degree atomics over dst (4 e/t); LAST block sorts breakpoints ------
// The sort block is independent of the atomics and hides under the ~20us
// atomic pass; it must only complete before k_distab (next launch).
__global__ void __launch_bounds__(256, 8) k_deg(const void* __restrict__ edges, int E,
                                                const float* __restrict__ W1,
                                                const float* __restrict__ b1) {
    if (blockIdx.x == gridDim.x - 1) {
        int t = threadIdx.x;
        __shared__ float key[HID];
        __shared__ int   idx[HID];
        // relu(s*w+b) crossing for s>0: thr=-b/w if (w>0,b<0) or (w<0,b>0)
        float w = W1[t], b = b1[t];
        float thr = 3.0e38f;
        if ((w > 0.f && b < 0.f) || (w < 0.f && b > 0.f)) thr = -b / w;
        key[t] = thr; idx[t] = t;
        __syncthreads();
        for (int k = 2; k <= HID; k <<= 1) {
            for (int j = k >> 1; j > 0; j >>= 1) {
                int p = t ^ j;
                if (p > t) {
                    bool up = ((t & k) == 0);
                    float ka = key[t], kb = key[p];
                    if ((ka > kb) == up) {
                        key[t] = kb; key[p] = ka;
                        int ia = idx[t]; idx[t] = idx[p]; idx[p] = ia;
                    }
                }
                __syncthreads();
            }
        }
        g_thr[t] = key[t];
        g_sidx[t] = idx[t];
        return;
    }

    int is32 = edges_is32(edges);
    int i = (blockIdx.x * blockDim.x + threadIdx.x) * 4;
    if (i >= E) return;
    if (is32) {
        const int* p = (const int*)edges + E;  // dst half
        if (i + 4 <= E) {
            int4 v = __ldg((const int4*)(p + i));
            atomicAdd(&g_degc[v.x], 1); atomicAdd(&g_degc[v.y], 1);
            atomicAdd(&g_degc[v.z], 1); atomicAdd(&g_degc[v.w], 1);
        } else {
            for (int j = i; j < E; j++) atomicAdd(&g_degc[p[j]], 1);
        }
    } else {
        const long long* p = (const long long*)edges + E;
        if (i + 4 <= E) {
            const int4* q = (const int4*)(p + i);
            int4 a = __ldg(q), b = __ldg(q + 1);
            atomicAdd(&g_degc[a.x], 1); atomicAdd(&g_degc[a.z], 1);
            atomicAdd(&g_degc[b.x], 1); atomicAdd(&g_degc[b.z], 1);
        } else {
            for (int j = i; j < E; j++) atomicAdd(&g_degc[(int)p[j]], 1);
        }
    }
}

// ---- K2 union: blocks [0,disBlocks) quantize dis AND zero g_tq; remaining
//      EMB blocks build per-interval tables. One wave, overlapped. ------------
// g_tq is first consumed by k_scat (next launch), so zeroing it here is safe.
__global__ void k_distab(int N, int disBlocks,
                         const float* __restrict__ W1, const float* __restrict__ b1,
                         const float* __restrict__ W2, const float* __restrict__ b2) {
    if (blockIdx.x < disBlocks) {
        int n = (blockIdx.x * blockDim.x + threadIdx.x) * 4;
        if (n >= N) return;
        if (n + 4 <= N) {
            int4 c = *(const int4*)&g_degc[n];
            unsigned int q0 = __float2uint_rn(rsqrtf((float)(c.x + 1)) * QS);
            unsigned int q1 = __float2uint_rn(rsqrtf((float)(c.y + 1)) * QS);
            unsigned int q2 = __float2uint_rn(rsqrtf((float)(c.z + 1)) * QS);
            unsigned int q3 = __float2uint_rn(rsqrtf((float)(c.w + 1)) * QS);
            *(uint2*)&g_disq[n] = make_uint2(q0 | (q1 << 16), q2 | (q3 << 16));
            *(uint4*)&g_tq[n] = make_uint4(0u, 0u, 0u, 0u);
        } else {
            for (int m = n; m < N; m++) {
                g_disq[m] = (unsigned short)__float2uint_rn(rsqrtf((float)(g_degc[m] + 1)) * QS);
                g_tq[m] = 0u;
            }
        }
        return;
    }

    // ---- table-build block (column j): base + delta prefix-scan -------------
    __shared__ float sa[HID], sc[HID];  // deltas -> scan
    __shared__ float ra[HID], rc[HID];  // base terms -> reduction
    int j = blockIdx.x - disBlocks;
    int t = threadIdx.x;
    if (t >= HID) return;

    float w = W1[t], b = b1[t];
    float w2 = __ldg(&W2[t * EMB + j]);
    bool act = (b > 0.f) || (b == 0.f && w > 0.f);
    ra[t] = act ? w * w2 : 0.f;
    rc[t] = act ? b * w2 : 0.f;

    // delta at sorted position t (toggled term is exactly 0 at its breakpoint
    // => interval boundary handling is value-exact)
    int h = g_sidx[t];
    float wh = W1[h], bh = b1[h];
    float w2h = __ldg(&W2[h * EMB + j]);
    float d = (wh > 0.f && bh < 0.f) ? 1.f : ((wh < 0.f && bh > 0.f) ? -1.f : 0.f);
    sa[t] = d * wh * w2h;
    sc[t] = d * bh * w2h;
    __syncthreads();

    #pragma unroll
    for (int s = HID / 2; s > 0; s >>= 1) {
        if (t < s) { ra[t] += ra[t + s]; rc[t] += rc[t + s]; }
        __syncthreads();
    }
    float A0 = ra[0];
    float C0 = rc[0] + b2[j];

    #pragma unroll
    for (int off = 1; off < HID; off <<= 1) {
        float va = 0.f, vc = 0.f;
        if (t >= off) { va = sa[t - off]; vc = sc[t - off]; }
        __syncthreads();
        if (t >= off) { sa[t] += va; sc[t] += vc; }
        __syncthreads();
    }

    if (t == 0) g_tab[j] = make_float2(A0, C0);
    g_tab[(t + 1) * EMB + j] = make_float2(A0 + sa[t], C0 + sc[t]);
}

// ---- K3: tq[dst] += disq[src]  (u16 L1 gather + u32 L2 atomic) --------------
__device__ __forceinline__ void scat1(int src, int dst) {
    unsigned int q = (unsigned int)__ldg(&g_disq[src]);
    atomicAdd(&g_tq[dst], q);
}
__global__ void __launch_bounds__(256, 8) k_scat(const void* __restrict__ edges, int E) {
    int is32 = edges_is32(edges);
    int i = (blockIdx.x * blockDim.x + threadIdx.x) * 4;
    if (i >= E) return;
    if (is32) {
        const int* ps = (const int*)edges;
        const int* pd = ps + E;
        if (i + 4 <= E) {
            int4 s = __ldcs((const int4*)(ps + i));
            int4 d = __ldg((const int4*)(pd + i));
            scat1(s.x, d.x); scat1(s.y, d.y); scat1(s.z, d.z); scat1(s.w, d.w);
        } else {
            for (int j = i; j < E; j++) scat1(ps[j], pd[j]);
        }
    } else {
        const long long* ps = (const long long*)edges;
        const long long* pd = ps + E;
        if (i + 4 <= E) {
            const int4* qs = (const int4*)(ps + i);
            const int4* qd = (const int4*)(pd + i);
            int4 s0 = __ldcs(qs), s1 = __ldcs(qs + 1);
            int4 d0 = __ldg(qd),  d1 = __ldg(qd + 1);
            scat1(s0.x, d0.x); scat1(s0.z, d0.z);
            scat1(s1.x, d1.x); scat1(s1.z, d1.z);
        } else {
            for (int j = i; j < E; j++) scat1((int)ps[j], (int)pd[j]);
        }
    }
}

// ---- K4: output. grid (nodeBlocks, 4): each thread 2 nodes x 32 columns -----
__global__ void k_out(float* __restrict__ out, int N) {
    __shared__ float sthr[HID];
    for (int i = threadIdx.x; i < HID; i += blockDim.x) sthr[i] = g_thr[i];
    __syncthreads();

    int n0 = (blockIdx.x * blockDim.x + threadIdx.x) * 2;
    if (n0 >= N) return;
    int jbase = blockIdx.y * (EMB / 4);   // 32 columns per y-slice
    bool has2 = (n0 + 1 < N) && ((N & 1) == 0);
    int n1 = has2 ? n0 + 1 : n0;

    float d0 = rsqrtf((float)(g_degc[n0] + 1));
    float d1 = rsqrtf((float)(g_degc[n1] + 1));
    float s0 = d0 * ((float)g_tq[n0] * QI + d0);
    float s1 = d1 * ((float)g_tq[n1] * QI + d1);

    int lo0 = 0, hi0 = HID, lo1 = 0, hi1 = HID;
    #pragma unroll
    for (int it = 0; it < 8; it++) {
        int m0 = (lo0 + hi0) >> 1;
        if (sthr[m0] < s0) lo0 = m0 + 1; else hi0 = m0;
        int m1 = (lo1 + hi1) >> 1;
        if (sthr[m1] < s1) lo1 = m1 + 1; else hi1 = m1;
    }

    const float4* __restrict__ r0 = (const float4*)(g_tab + lo0 * EMB + jbase);
    const float4* __restrict__ r1 = (const float4*)(g_tab + lo1 * EMB + jbase);

    if (has2) {
        #pragma unroll
        for (int jj = 0; jj < EMB / 8; jj++) {       // 16 iters x 2 columns
            float4 va = __ldg(&r0[jj]);
            float4 vb = __ldg(&r1[jj]);
            float xa0 = fmaf(s0, va.x, va.y), xa1 = fmaf(s0, va.z, va.w);
            float xb0 = fmaf(s1, vb.x, vb.y), xb1 = fmaf(s1, vb.z, vb.w);
            float ya0 = __fdividef(1.f, 1.f + __expf(-xa0));
            float ya1 = __fdividef(1.f, 1.f + __expf(-xa1));
            float yb0 = __fdividef(1.f, 1.f + __expf(-xb0));
            float yb1 = __fdividef(1.f, 1.f + __expf(-xb1));
            int j = jbase + jj * 2;
            *(float2*)&out[j * N + n0]       = make_float2(ya0, yb0);
            *(float2*)&out[(j + 1) * N + n0] = make_float2(ya1, yb1);
        }
    } else {
        #pragma unroll
        for (int jj = 0; jj < EMB / 8; jj++) {
            float4 va = __ldg(&r0[jj]);
            float xa0 = fmaf(s0, va.x, va.y), xa1 = fmaf(s0, va.z, va.w);
            int j = jbase + jj * 2;
            out[j * N + n0]       = __fdividef(1.f, 1.f + __expf(-xa0));
            out[(j + 1) * N + n0] = __fdividef(1.f, 1.f + __expf(-xa1));
        }
    }
}

// ---------------- launch (pure kernel launches; no host API calls) ------------
extern "C" void kernel_launch(void* const* d_in, const int* in_sizes, int n_in,
                              void* d_out, int out_size) {
    const void*  edges = d_in[0];
    const float* W1    = (const float*)d_in[1];
    const float* b1    = (const float*)d_in[2];
    const float* W2    = (const float*)d_in[3];
    const float* b2    = (const float*)d_in[4];
    int E = in_sizes[0] / 2;
    int N = out_size / EMB;
    if (N > NMAX) N = NMAX;

    const int TB = 256;
    int gZ = (N + TB * 4 - 1) / (TB * 4);
    int gE = (E + TB * 4 - 1) / (TB * 4);
    int gD = (N + TB * 4 - 1) / (TB * 4);
    int gO = (N + TB * 2 - 1) / (TB * 2);

    k_zero  <<<gZ, TB>>>(N);
    k_deg   <<<gE + 1, TB>>>(edges, E, W1, b1);
    k_distab<<<gD + EMB, TB>>>(N, gD, W1, b1, W2, b2);
    k_scat  <<<gE, TB>>>(edges, E);
    k_out   <<<dim3(gO, 4), TB>>>((float*)d_out, N);
}